// round 13
// baseline (speedup 1.0000x reference)
#include <cuda_runtime.h>
#include <cuda_bf16.h>
#include <cstdint>

typedef unsigned long long u64;

#define B_   16
#define T_   1024
#define E_   128
#define H_   256
#define G4_  1024
#define NC_  8000
#define NPAD 8064
#define NB   4          // batches per cluster (latency hiding)

// -------- scratch (static device arrays) ----------
__device__ float g_xproj[(size_t)T_ * B_ * G4_];   // [t][b][g] == [16384][1024]
__device__ float g_hs[(size_t)B_ * T_ * H_];       // [b][t][h] == A [16384][256]
__device__ int   g_xlong;
__device__ __nv_bfloat16 g_Ah[(size_t)B_ * T_ * H_];
__device__ __nv_bfloat16 g_Al[(size_t)B_ * T_ * H_];
__device__ __nv_bfloat16 g_Bh[(size_t)NPAD * H_];
__device__ __nv_bfloat16 g_Bl[(size_t)NPAD * H_];
__device__ __nv_bfloat16 g_Ih[(size_t)T_ * B_ * H_];   // inp hi  [16384][256]
__device__ __nv_bfloat16 g_Il[(size_t)T_ * B_ * H_];   // inp lo
__device__ __nv_bfloat16 g_Wh[(size_t)G4_ * H_];       // W_ih hi [1024][256]
__device__ __nv_bfloat16 g_Wl[(size_t)G4_ * H_];       // W_ih lo

// -------- packed f32x2 helpers ----------
__device__ __forceinline__ void ffma2(u64 &d, u64 a, u64 b) {
    asm("fma.rn.f32x2 %0, %1, %2, %0;" : "+l"(d) : "l"(a), "l"(b));
}
__device__ __forceinline__ u64 fpack(float x, float y) {
    u64 r; asm("mov.b64 %0, {%1, %2};" : "=l"(r) : "f"(x), "f"(y)); return r;
}
__device__ __forceinline__ float2 funpack(u64 v) {
    float2 r; asm("mov.b64 {%0, %1}, %2;" : "=f"(r.x), "=f"(r.y) : "l"(v)); return r;
}
__device__ __forceinline__ float sigm(float x) { return 1.0f / (1.0f + __expf(-x)); }
__device__ __forceinline__ float tanh_f(float x) { return 2.0f * sigm(2.0f * x) - 1.0f; }

// -------- cluster / mbarrier helpers ----------
__device__ __forceinline__ uint32_t smem_u32(const void *p) {
    return (uint32_t)__cvta_generic_to_shared(p);
}
__device__ __forceinline__ uint32_t mapa_u32(uint32_t a, uint32_t rank) {
    uint32_t r;
    asm("mapa.shared::cluster.u32 %0, %1, %2;" : "=r"(r) : "r"(a), "r"(rank));
    return r;
}
__device__ __forceinline__ void mbar_init(uint32_t mbar, uint32_t cnt) {
    asm volatile("mbarrier.init.shared.b64 [%0], %1;" :: "r"(mbar), "r"(cnt) : "memory");
}
__device__ __forceinline__ void mbar_expect_tx(uint32_t mbar, uint32_t bytes) {
    asm volatile("mbarrier.arrive.expect_tx.shared.b64 _, [%0], %1;" :: "r"(mbar), "r"(bytes) : "memory");
}
__device__ __forceinline__ void mbar_wait(uint32_t mbar, uint32_t parity) {
    asm volatile(
        "{\n\t.reg .pred P;\n\t"
        "WL_%=:\n\t"
        "mbarrier.try_wait.parity.acquire.cta.shared::cta.b64 P, [%0], %1, 0x989680;\n\t"
        "@P bra.uni WD_%=;\n\t"
        "bra.uni WL_%=;\n\t"
        "WD_%=:\n\t}"
        :: "r"(mbar), "r"(parity) : "memory");
}
__device__ __forceinline__ void st_async_u64(uint32_t addr, u64 v, uint32_t mbar) {
    asm volatile("st.async.shared::cluster.mbarrier::complete_tx::bytes.b64 [%0], %1, [%2];"
                 :: "r"(addr), "l"(v), "r"(mbar) : "memory");
}
__device__ __forceinline__ void lds_v2u64(uint32_t a, u64 &x, u64 &y) {
    asm("ld.shared.v2.u64 {%0, %1}, [%2];" : "=l"(x), "=l"(y) : "r"(a));
}
#define CLUSTER_SYNC() do { \
    asm volatile("barrier.cluster.arrive.aligned;" ::: "memory"); \
    asm volatile("barrier.cluster.wait.aligned;" ::: "memory"); } while (0)

// -------- bf16 mma ----------
__device__ __forceinline__ void mma_bf16(float *d, const uint32_t *a, const uint32_t *b) {
    asm("mma.sync.aligned.m16n8k16.row.col.f32.bf16.bf16.f32 "
        "{%0,%1,%2,%3}, {%4,%5,%6,%7}, {%8,%9}, {%0,%1,%2,%3};"
        : "+f"(d[0]), "+f"(d[1]), "+f"(d[2]), "+f"(d[3])
        : "r"(a[0]), "r"(a[1]), "r"(a[2]), "r"(a[3]), "r"(b[0]), "r"(b[1]));
}

// ===========================================================================
// K0: detect x dtype (int64 vs int32)
// ===========================================================================
__global__ void k_init(const void *xraw) {
    if (threadIdx.x == 0) {
        const unsigned int *xi = (const unsigned int *)xraw;
        int i64 = 1;
        for (int i = 0; i < 64; i++)
            if (xi[2 * i + 1] != 0u) { i64 = 0; break; }
        g_xlong = i64;
    }
}

// ===========================================================================
// K1a: embedding gather -> bf16 hi/lo input matrix, t-major rows (m = t*16+b)
// ===========================================================================
__global__ void __launch_bounds__(256) k_gather(
    const void *xraw, const float *embx, const float *embl)
{
    const int t = blockIdx.x;
    __shared__ int xs[B_], ls[B_];
    const int tid = threadIdx.x;

    if (tid < 32) {
        int b = tid >> 1, j = tid & 1;
        long long e = (long long)b * (T_ * 2) + t * 2 + j;
        int v;
        if (g_xlong) v = (int)((const long long *)xraw)[e];
        else         v = ((const int *)xraw)[e];
        if (j == 0) xs[b] = v; else ls[b] = v;
    }
    __syncthreads();

    for (int idx = tid; idx < B_ * 256; idx += 256) {
        int b = idx >> 8, k = idx & 255;
        float v = (k < E_) ? embx[xs[b] * E_ + k] : embl[ls[b] * E_ + (k - E_)];
        __nv_bfloat16 h = __float2bfloat16(v);
        __nv_bfloat16 lo = __float2bfloat16(v - __bfloat162float(h));
        size_t e = ((size_t)t * B_ + b) * 256 + k;
        g_Ih[e] = h;
        g_Il[e] = lo;
    }
}

// ===========================================================================
// K1b: W_ih -> bf16 hi/lo
// ===========================================================================
__global__ void __launch_bounds__(256) k_splitW(const float *Wih)
{
    for (int idx = blockIdx.x * 256 + threadIdx.x; idx < (G4_ * H_) / 4;
         idx += gridDim.x * 256) {
        float4 v = ((const float4 *)Wih)[idx];
        size_t e = (size_t)idx * 4;
        __nv_bfloat162 h01 = __floats2bfloat162_rn(v.x, v.y);
        __nv_bfloat162 h23 = __floats2bfloat162_rn(v.z, v.w);
        __nv_bfloat162 l01 = __floats2bfloat162_rn(v.x - __bfloat162float(h01.x),
                                                   v.y - __bfloat162float(h01.y));
        __nv_bfloat162 l23 = __floats2bfloat162_rn(v.z - __bfloat162float(h23.x),
                                                   v.w - __bfloat162float(h23.y));
        *(__nv_bfloat162 *)(g_Wh + e)     = h01;
        *(__nv_bfloat162 *)(g_Wh + e + 2) = h23;
        *(__nv_bfloat162 *)(g_Wl + e)     = l01;
        *(__nv_bfloat162 *)(g_Wl + e + 2) = l23;
    }
}

// ===========================================================================
// K1c: input projection GEMM via bf16x3 tensor cores (3-stage cp.async).
// ===========================================================================
#define BSTRD 24
#define STAGE_ELEMS (4 * 128 * BSTRD)

__global__ void __launch_bounds__(256) k_proj(const float *bih, const float *bhh)
{
    extern __shared__ __align__(16) __nv_bfloat16 smd[];

    const int bn = blockIdx.x * 128;
    const int bm = blockIdx.y * 128;

    const int tid = threadIdx.x;
    const int w = tid >> 5, l = tid & 31;
    const int wm = w & 1, wn = w >> 1;
    const int g = l >> 2, tig = l & 3;

    float acc[4][4][4];
#pragma unroll
    for (int i = 0; i < 4; i++)
#pragma unroll
        for (int j = 0; j < 4; j++)
#pragma unroll
            for (int c = 0; c < 4; c++) acc[i][j][c] = 0.0f;

    const __nv_bfloat16 *gsrc0 = g_Ih + (size_t)bm * H_;
    const __nv_bfloat16 *gsrc1 = g_Il + (size_t)bm * H_;
    const __nv_bfloat16 *gsrc2 = g_Wh + (size_t)bn * H_;
    const __nv_bfloat16 *gsrc3 = g_Wl + (size_t)bn * H_;

#define LOAD_CHUNK_P(kc, st) do {                                            \
    int k0 = (kc) * 16;                                                      \
    _Pragma("unroll")                                                        \
    for (int i = 0; i < 4; i++) {                                            \
        int s = i * 256 + tid;                                               \
        int tile = s >> 8;                                                   \
        int rr = (s >> 1) & 127;                                             \
        int cc = s & 1;                                                      \
        const __nv_bfloat16 *src =                                           \
            (tile == 0 ? gsrc0 : tile == 1 ? gsrc1 : tile == 2 ? gsrc2 : gsrc3) \
            + (size_t)rr * H_ + k0 + cc * 8;                                 \
        uint32_t dst = smem_u32(smd + (st) * STAGE_ELEMS                     \
                                + tile * (128 * BSTRD) + rr * BSTRD + cc * 8); \
        asm volatile("cp.async.cg.shared.global [%0], [%1], 16;"             \
                     :: "r"(dst), "l"(src));                                 \
    }                                                                        \
    asm volatile("cp.async.commit_group;");                                  \
} while (0)

    LOAD_CHUNK_P(0, 0);
    LOAD_CHUNK_P(1, 1);
    int st = 0, ld_st = 2;
    for (int kc = 0; kc < 16; kc++) {
        if (kc < 15) asm volatile("cp.async.wait_group 1;");
        else         asm volatile("cp.async.wait_group 0;");
        __syncthreads();
        if (kc + 2 < 16) {
            LOAD_CHUNK_P(kc + 2, ld_st);
            ld_st = (ld_st == 2) ? 0 : ld_st + 1;
        }

        const __nv_bfloat16 *Ah_s = smd + st * STAGE_ELEMS;
        const __nv_bfloat16 *Al_s = Ah_s + 128 * BSTRD;
        const __nv_bfloat16 *Bh_s = Ah_s + 2 * 128 * BSTRD;
        const __nv_bfloat16 *Bl_s = Ah_s + 3 * 128 * BSTRD;

        uint32_t ah[4][4], al[4][4], bh[4][2], bl[4][2];
#pragma unroll
        for (int i = 0; i < 4; i++) {
            int arow = (wm * 64 + i * 16 + g) * BSTRD + 2 * tig;
            ah[i][0] = *(const uint32_t *)(Ah_s + arow);
            ah[i][1] = *(const uint32_t *)(Ah_s + arow + 8 * BSTRD);
            ah[i][2] = *(const uint32_t *)(Ah_s + arow + 8);
            ah[i][3] = *(const uint32_t *)(Ah_s + arow + 8 * BSTRD + 8);
            al[i][0] = *(const uint32_t *)(Al_s + arow);
            al[i][1] = *(const uint32_t *)(Al_s + arow + 8 * BSTRD);
            al[i][2] = *(const uint32_t *)(Al_s + arow + 8);
            al[i][3] = *(const uint32_t *)(Al_s + arow + 8 * BSTRD + 8);
        }
#pragma unroll
        for (int j = 0; j < 4; j++) {
            int brow = (wn * 32 + j * 8 + g) * BSTRD + 2 * tig;
            bh[j][0] = *(const uint32_t *)(Bh_s + brow);
            bh[j][1] = *(const uint32_t *)(Bh_s + brow + 8);
            bl[j][0] = *(const uint32_t *)(Bl_s + brow);
            bl[j][1] = *(const uint32_t *)(Bl_s + brow + 8);
        }
#pragma unroll
        for (int i = 0; i < 4; i++)
#pragma unroll
            for (int j = 0; j < 4; j++) {
                mma_bf16(acc[i][j], ah[i], bh[j]);
                mma_bf16(acc[i][j], al[i], bh[j]);
                mma_bf16(acc[i][j], ah[i], bl[j]);
            }

        st = (st == 2) ? 0 : st + 1;
    }

#pragma unroll
    for (int i = 0; i < 4; i++) {
        int m0 = bm + wm * 64 + i * 16 + g;
#pragma unroll
        for (int j = 0; j < 4; j++) {
            int n0 = bn + wn * 32 + j * 8 + 2 * tig;
            float bx = bih[n0] + bhh[n0];
            float by = bih[n0 + 1] + bhh[n0 + 1];
            *(float2 *)(g_xproj + (size_t)m0 * G4_ + n0) =
                make_float2(acc[i][j][0] + bx, acc[i][j][1] + by);
            *(float2 *)(g_xproj + (size_t)(m0 + 8) * G4_ + n0) =
                make_float2(acc[i][j][2] + bx, acc[i][j][3] + by);
        }
    }
}

// ===========================================================================
// K2: LSTM — round-3 protocol, NB=4 batches interleaved per cluster.
// 4 clusters x 8 CTAs. Per step, per batch bb (serial within CTA):
//   wait mbar[bb][p] -> re-arm -> dot(h_buf[bb]) -> gates_s[bb] -> sync ->
//   act -> send to peers' h_buf[bb][nb] (st.async, mbar[bb][nb]).
// While batch bb's DSMEM broadcast is in flight, the CTA computes the other
// three batches -> the ~3.5K-cycle latency chain is hidden behind compute.
// ===========================================================================
__global__ void __launch_bounds__(512, 1) __cluster_dims__(8, 1, 1)
k_lstm(const float *Whh)
{
    const int cta = blockIdx.x;
    const int b0  = (cta >> 3) * NB;
    const int grp = cta & 7;
    const int tid = threadIdx.x;
    const int r = tid >> 2;        // 0..127 local row = gate*32 + lh
    const int q = tid & 3;         // K quarter (64 floats each)
    const int gate = r >> 5, lh = r & 31;
    const int row_g = gate * H_ + grp * 32 + lh;

    __shared__ __align__(16) float h_buf[NB][2][272];   // [batch][buf][4q*68]
    __shared__ float gates_s[NB][128];
    __shared__ __align__(8) u64 mbar[NB][2];            // [batch][phase]

    // W_hh slice into registers (shared across batches)
    u64 w2[32];
    {
        const float *wp = Whh + (size_t)row_g * H_ + q * 64;
#pragma unroll
        for (int j = 0; j < 32; j++) w2[j] = *(const u64 *)(wp + 2 * j);
    }

    // zero all h buffers
    for (int i = tid; i < (NB * 2 * 272) / 4; i += 512)
        ((float4 *)h_buf)[i] = make_float4(0.f, 0.f, 0.f, 0.f);

    const uint32_t mbase = smem_u32(&mbar[0][0]);
    const uint32_t hbase = smem_u32(&h_buf[0][0][0]);
    if (tid < NB * 2) mbar_init(mbase + (uint32_t)tid * 8, 1);
    __syncthreads();
    if (tid < NB * 2) mbar_expect_tx(mbase + (uint32_t)tid * 8, 1024);

    // producer peer addresses (lanes 0..15 store f32x2 pairs)
    uint32_t peer_h[8], peer_m[8];
    {
        int k = grp * 32 + 2 * (tid & 15);
        uint32_t off = (uint32_t)(((k >> 6) * 68 + (k & 63)) * 4);
        uint32_t hb = hbase;
#pragma unroll
        for (int pc = 0; pc < 8; pc++) {
            peer_h[pc] = mapa_u32(hb, (uint32_t)pc) + off;
            peer_m[pc] = mapa_u32(mbase, (uint32_t)pc);
        }
    }

    float xp[NB], creg[NB];
#pragma unroll
    for (int bb = 0; bb < NB; bb++) {
        xp[bb]   = (q == 0) ? g_xproj[(size_t)(b0 + bb) * G4_ + row_g] : 0.0f;
        creg[bb] = 0.0f;
    }
    __syncthreads();
    CLUSTER_SYNC();   // mbarriers initialized cluster-wide before any st.async

    uint32_t ph0 = 0, ph1 = 0;

    for (int t = 0; t < T_; t++) {
        const int p = t & 1;
        const uint32_t bo  = (uint32_t)p * 1088;           // read buffer
        const uint32_t nbo = (uint32_t)((t + 1) & 1) * 1088;  // write buffer
        const uint32_t mo  = (uint32_t)((t + 1) & 1) * 8;     // send-target mbar

#pragma unroll
        for (int bb = 0; bb < NB; bb++) {
            const uint32_t hb_b = hbase + (uint32_t)bb * 2176;
            const uint32_t mb_b = mbase + (uint32_t)bb * 16;

            if (t > 0) {
                uint32_t mb = mb_b + (uint32_t)p * 8;
                mbar_wait(mb, p ? ph1 : ph0);
                if (tid == 0 && t + 2 < T_) mbar_expect_tx(mb, 1024);
            }

            // dot product over this thread's 64-float quarter
            uint32_t hq = hb_b + bo + (uint32_t)q * 272;
            u64 a0 = 0, a1 = 0, a2 = 0, a3 = 0;
#pragma unroll
            for (int jj = 0; jj < 16; jj += 2) {
                u64 x0, y0, x1, y1;
                lds_v2u64(hq + jj * 16, x0, y0);
                lds_v2u64(hq + jj * 16 + 16, x1, y1);
                ffma2(a0, w2[2 * jj + 0], x0);
                ffma2(a1, w2[2 * jj + 1], y0);
                ffma2(a2, w2[2 * jj + 2], x1);
                ffma2(a3, w2[2 * jj + 3], y1);
            }
            float2 s0 = funpack(a0), s1 = funpack(a1), s2 = funpack(a2), s3 = funpack(a3);
            float sum = ((s0.x + s0.y) + (s1.x + s1.y)) + ((s2.x + s2.y) + (s3.x + s3.y));
            sum += __shfl_xor_sync(0xffffffffu, sum, 1);
            sum += __shfl_xor_sync(0xffffffffu, sum, 2);
            if (q == 0) gates_s[bb][r] = sum + xp[bb];

            // prefetch next step's xp for this batch
            if (q == 0 && t + 1 < T_)
                xp[bb] = g_xproj[(size_t)(t + 1) * (B_ * G4_) + (b0 + bb) * G4_ + row_g];

            __syncthreads();

            if (tid < 32) {
                float iv = sigm(gates_s[bb][tid]);
                float fv = sigm(gates_s[bb][32 + tid]);
                float gv = tanh_f(gates_s[bb][64 + tid]);
                float ov = sigm(gates_s[bb][96 + tid]);
                float cn = fv * creg[bb] + iv * gv;
                creg[bb] = cn;
                float hn = ov * tanh_f(cn);
                g_hs[((size_t)(b0 + bb) * T_ + t) * H_ + grp * 32 + tid] = hn;
                float he = __shfl_sync(0xffffffffu, hn, 2 * (tid & 15));
                float ho = __shfl_sync(0xffffffffu, hn, 2 * (tid & 15) + 1);
                if (tid < 16 && t < T_ - 1) {
                    u64 hv2 = fpack(he, ho);
#pragma unroll
                    for (int pc = 0; pc < 8; pc++)
                        st_async_u64(peer_h[pc] + (uint32_t)bb * 2176 + nbo, hv2,
                                     peer_m[pc] + (uint32_t)bb * 16 + mo);
                }
            }
        }

        if (t > 0) { if (p) ph1 ^= 1; else ph0 ^= 1; }
    }
    CLUSTER_SYNC();
}

// ===========================================================================
// K2.5: split fp32 -> bf16 hi/lo for A (g_hs) and B (fc_w, padded to 8064)
// ===========================================================================
#define TOT4A ((B_ * T_ * H_) / 4)
#define TOT4B ((NPAD * H_) / 4)

__global__ void __launch_bounds__(256) k_split(const float *fcw)
{
    for (size_t idx = (size_t)blockIdx.x * blockDim.x + threadIdx.x;
         idx < TOT4A + TOT4B; idx += (size_t)gridDim.x * blockDim.x) {
        float4 v;
        __nv_bfloat16 *dh, *dl;
        size_t e;
        if (idx < TOT4A) {
            v = ((const float4 *)g_hs)[idx];
            e = idx * 4; dh = g_Ah; dl = g_Al;
        } else {
            size_t j = idx - TOT4A;
            e = j * 4;
            int n = (int)(e >> 8), k = (int)(e & 255);
            if (n < NC_) v = *(const float4 *)(fcw + (size_t)n * H_ + k);
            else         v = make_float4(0.f, 0.f, 0.f, 0.f);
            dh = g_Bh; dl = g_Bl;
        }
        __nv_bfloat162 h01 = __floats2bfloat162_rn(v.x, v.y);
        __nv_bfloat162 h23 = __floats2bfloat162_rn(v.z, v.w);
        float lx = v.x - __bfloat162float(h01.x);
        float ly = v.y - __bfloat162float(h01.y);
        float lz = v.z - __bfloat162float(h23.x);
        float lw = v.w - __bfloat162float(h23.y);
        __nv_bfloat162 l01 = __floats2bfloat162_rn(lx, ly);
        __nv_bfloat162 l23 = __floats2bfloat162_rn(lz, lw);
        *(__nv_bfloat162 *)(dh + e)     = h01;
        *(__nv_bfloat162 *)(dh + e + 2) = h23;
        *(__nv_bfloat162 *)(dl + e)     = l01;
        *(__nv_bfloat162 *)(dl + e + 2) = l23;
    }
}

// ===========================================================================
// K3: FC GEMM via bf16x3 tensor cores — 3-stage cp.async pipeline.
// ===========================================================================
__global__ void __launch_bounds__(256) k_fc(const float *fcb, float *out)
{
    extern __shared__ __align__(16) __nv_bfloat16 smd[];

    const int bn = blockIdx.x * 128;
    const int bm = blockIdx.y * 128;

    const int tid = threadIdx.x;
    const int w = tid >> 5, l = tid & 31;
    const int wm = w & 1, wn = w >> 1;
    const int g = l >> 2, tig = l & 3;

    float acc[4][4][4];
#pragma unroll
    for (int i = 0; i < 4; i++)
#pragma unroll
        for (int j = 0; j < 4; j++)
#pragma unroll
            for (int c = 0; c < 4; c++) acc[i][j][c] = 0.0f;

    const __nv_bfloat16 *gsrc0 = g_Ah + (size_t)bm * H_;
    const __nv_bfloat16 *gsrc1 = g_Al + (size_t)bm * H_;
    const __nv_bfloat16 *gsrc2 = g_Bh + (size_t)bn * H_;
    const __nv_bfloat16 *gsrc3 = g_Bl + (size_t)bn * H_;

#define LOAD_CHUNK(kc, st) do {                                              \
    int k0 = (kc) * 16;                                                      \
    _Pragma("unroll")                                                        \
    for (int i = 0; i < 4; i++) {                                            \
        int s = i * 256 + tid;                                               \
        int tile = s >> 8;                                                   \
        int rr = (s >> 1) & 127;                                             \
        int cc = s & 1;                                                      \
        const __nv_bfloat16 *src =                                           \
            (tile == 0 ? gsrc0 : tile == 1 ? gsrc1 : tile == 2 ? gsrc2 : gsrc3) \
            + (size_t)rr * H_ + k0 + cc * 8;                                 \
        uint32_t dst = smem_u32(smd + (st) * STAGE_ELEMS                     \
                                + tile * (128 * BSTRD) + rr * BSTRD + cc * 8); \
        asm volatile("cp.async.cg.shared.global [%0], [%1], 16;"             \
                     :: "r"(dst), "l"(src));                                 \
    }                                                                        \
    asm volatile("cp.async.commit_group;");                                  \
} while (0)

    LOAD_CHUNK(0, 0);
    LOAD_CHUNK(1, 1);
    int st = 0, ld_st = 2;
    for (int kc = 0; kc < 16; kc++) {
        if (kc < 15) asm volatile("cp.async.wait_group 1;");
        else         asm volatile("cp.async.wait_group 0;");
        __syncthreads();
        if (kc + 2 < 16) {
            LOAD_CHUNK(kc + 2, ld_st);
            ld_st = (ld_st == 2) ? 0 : ld_st + 1;
        }

        const __nv_bfloat16 *Ah_s = smd + st * STAGE_ELEMS;
        const __nv_bfloat16 *Al_s = Ah_s + 128 * BSTRD;
        const __nv_bfloat16 *Bh_s = Ah_s + 2 * 128 * BSTRD;
        const __nv_bfloat16 *Bl_s = Ah_s + 3 * 128 * BSTRD;

        uint32_t ah[4][4], al[4][4], bh[4][2], bl[4][2];
#pragma unroll
        for (int i = 0; i < 4; i++) {
            int arow = (wm * 64 + i * 16 + g) * BSTRD + 2 * tig;
            ah[i][0] = *(const uint32_t *)(Ah_s + arow);
            ah[i][1] = *(const uint32_t *)(Ah_s + arow + 8 * BSTRD);
            ah[i][2] = *(const uint32_t *)(Ah_s + arow + 8);
            ah[i][3] = *(const uint32_t *)(Ah_s + arow + 8 * BSTRD + 8);
            al[i][0] = *(const uint32_t *)(Al_s + arow);
            al[i][1] = *(const uint32_t *)(Al_s + arow + 8 * BSTRD);
            al[i][2] = *(const uint32_t *)(Al_s + arow + 8);
            al[i][3] = *(const uint32_t *)(Al_s + arow + 8 * BSTRD + 8);
        }
#pragma unroll
        for (int j = 0; j < 4; j++) {
            int brow = (wn * 32 + j * 8 + g) * BSTRD + 2 * tig;
            bh[j][0] = *(const uint32_t *)(Bh_s + brow);
            bh[j][1] = *(const uint32_t *)(Bh_s + brow + 8);
            bl[j][0] = *(const uint32_t *)(Bl_s + brow);
            bl[j][1] = *(const uint32_t *)(Bl_s + brow + 8);
        }
#pragma unroll
        for (int i = 0; i < 4; i++)
#pragma unroll
            for (int j = 0; j < 4; j++) {
                mma_bf16(acc[i][j], ah[i], bh[j]);
                mma_bf16(acc[i][j], al[i], bh[j]);
                mma_bf16(acc[i][j], ah[i], bl[j]);
            }

        st = (st == 2) ? 0 : st + 1;
    }

#pragma unroll
    for (int i = 0; i < 4; i++) {
        int m0 = bm + wm * 64 + i * 16 + g;
#pragma unroll
        for (int j = 0; j < 4; j++) {
            int n0 = bn + wn * 32 + j * 8 + 2 * tig;
            if (n0 < NC_) {
                float bx = fcb[n0], by = fcb[n0 + 1];
                *(float2 *)(out + (size_t)m0 * NC_ + n0) =
                    make_float2(acc[i][j][0] + bx, acc[i][j][1] + by);
                *(float2 *)(out + (size_t)(m0 + 8) * NC_ + n0) =
                    make_float2(acc[i][j][2] + bx, acc[i][j][3] + by);
            }
        }
    }
}

// ===========================================================================
extern "C" void kernel_launch(void *const *d_in, const int *in_sizes, int n_in,
                              void *d_out, int out_size)
{
    (void)in_sizes; (void)n_in; (void)out_size;
    const void  *x    = d_in[0];
    const float *embx = (const float *)d_in[1];
    const float *embl = (const float *)d_in[2];
    const float *Wih  = (const float *)d_in[3];
    const float *Whh  = (const float *)d_in[4];
    const float *bih  = (const float *)d_in[5];
    const float *bhh  = (const float *)d_in[6];
    const float *fcw  = (const float *)d_in[7];
    const float *fcb  = (const float *)d_in[8];
    float *out = (float *)d_out;

    const int fc_smem = 3 * STAGE_ELEMS * (int)sizeof(__nv_bfloat16);  // 73728
    cudaFuncSetAttribute(k_fc,   cudaFuncAttributeMaxDynamicSharedMemorySize, fc_smem);
    cudaFuncSetAttribute(k_proj, cudaFuncAttributeMaxDynamicSharedMemorySize, fc_smem);

    k_init<<<1, 32>>>(x);
    k_gather<<<T_, 256>>>(x, embx, embl);
    k_splitW<<<64, 256>>>(Wih);
    k_proj<<<dim3(G4_ / 128, (B_ * T_) / 128), 256, fc_smem>>>(bih, bhh);
    k_lstm<<<(B_ / NB) * 8, 512>>>(Whh);
    k_split<<<1024, 256>>>(fcw);
    k_fc<<<dim3(NPAD / 128, (B_ * T_) / 128), 256, fc_smem>>>(fcb, out);
}

// round 15
// speedup vs baseline: 1.6128x; 1.6128x over previous
#include <cuda_runtime.h>
#include <cuda_bf16.h>
#include <cstdint>

typedef unsigned long long u64;

#define B_   16
#define T_   1024
#define E_   128
#define H_   256
#define G4_  1024
#define NC_  8000
#define NPAD 8064
#define NTILE_N 63
#define NCHUNK  8           // 128-step chunks
#define NTICKETS (NCHUNK * B_ * NTILE_N)   // 8064 fc tiles

// -------- scratch (static device arrays) ----------
__device__ float g_xproj[(size_t)T_ * B_ * G4_];   // [t][b][g]
__device__ int   g_xlong;
__device__ int   g_prog[B_];
__device__ __nv_bfloat16 g_Ah[(size_t)B_ * T_ * H_];   // h hi  [m=b*1024+t][256]
__device__ __nv_bfloat16 g_Al[(size_t)B_ * T_ * H_];   // h lo
__device__ __nv_bfloat16 g_Bh[(size_t)NPAD * H_];
__device__ __nv_bfloat16 g_Bl[(size_t)NPAD * H_];
__device__ __nv_bfloat16 g_Ih[(size_t)T_ * B_ * H_];   // inp hi [m=t*16+b][256]
__device__ __nv_bfloat16 g_Il[(size_t)T_ * B_ * H_];
__device__ __nv_bfloat16 g_Wh[(size_t)G4_ * H_];
__device__ __nv_bfloat16 g_Wl[(size_t)G4_ * H_];

// -------- packed f32x2 helpers ----------
__device__ __forceinline__ void ffma2(u64 &d, u64 a, u64 b) {
    asm("fma.rn.f32x2 %0, %1, %2, %0;" : "+l"(d) : "l"(a), "l"(b));
}
__device__ __forceinline__ u64 fpack(float x, float y) {
    u64 r; asm("mov.b64 %0, {%1, %2};" : "=l"(r) : "f"(x), "f"(y)); return r;
}
__device__ __forceinline__ float2 funpack(u64 v) {
    float2 r; asm("mov.b64 {%0, %1}, %2;" : "=f"(r.x), "=f"(r.y) : "l"(v)); return r;
}
__device__ __forceinline__ float sigm(float x) { return 1.0f / (1.0f + __expf(-x)); }
__device__ __forceinline__ float tanh_f(float x) { return 2.0f * sigm(2.0f * x) - 1.0f; }

// -------- cluster / mbarrier helpers ----------
__device__ __forceinline__ uint32_t smem_u32(const void *p) {
    return (uint32_t)__cvta_generic_to_shared(p);
}
__device__ __forceinline__ uint32_t mapa_u32(uint32_t a, uint32_t rank) {
    uint32_t r;
    asm("mapa.shared::cluster.u32 %0, %1, %2;" : "=r"(r) : "r"(a), "r"(rank));
    return r;
}
__device__ __forceinline__ void mbar_init(uint32_t mbar, uint32_t cnt) {
    asm volatile("mbarrier.init.shared.b64 [%0], %1;" :: "r"(mbar), "r"(cnt) : "memory");
}
__device__ __forceinline__ void mbar_expect_tx(uint32_t mbar, uint32_t bytes) {
    asm volatile("mbarrier.arrive.expect_tx.shared.b64 _, [%0], %1;" :: "r"(mbar), "r"(bytes) : "memory");
}
__device__ __forceinline__ void mbar_wait(uint32_t mbar, uint32_t parity) {
    asm volatile(
        "{\n\t.reg .pred P;\n\t"
        "WL_%=:\n\t"
        "mbarrier.try_wait.parity.acquire.cta.shared::cta.b64 P, [%0], %1, 0x989680;\n\t"
        "@P bra.uni WD_%=;\n\t"
        "bra.uni WL_%=;\n\t"
        "WD_%=:\n\t}"
        :: "r"(mbar), "r"(parity) : "memory");
}
__device__ __forceinline__ void st_async_u64(uint32_t addr, u64 v, uint32_t mbar) {
    asm volatile("st.async.shared::cluster.mbarrier::complete_tx::bytes.b64 [%0], %1, [%2];"
                 :: "r"(addr), "l"(v), "r"(mbar) : "memory");
}
__device__ __forceinline__ void lds_v2u64(uint32_t a, u64 &x, u64 &y) {
    asm("ld.shared.v2.u64 {%0, %1}, [%2];" : "=l"(x), "=l"(y) : "r"(a));
}
__device__ __forceinline__ int ld_acq(const int *p) {
    int v; asm volatile("ld.acquire.gpu.s32 %0, [%1];" : "=r"(v) : "l"(p) : "memory");
    return v;
}
#define CLUSTER_SYNC() do { \
    asm volatile("barrier.cluster.arrive.aligned;" ::: "memory"); \
    asm volatile("barrier.cluster.wait.aligned;" ::: "memory"); } while (0)

// -------- bf16 mma ----------
__device__ __forceinline__ void mma_bf16(float *d, const uint32_t *a, const uint32_t *b) {
    asm("mma.sync.aligned.m16n8k16.row.col.f32.bf16.bf16.f32 "
        "{%0,%1,%2,%3}, {%4,%5,%6,%7}, {%8,%9}, {%0,%1,%2,%3};"
        : "+f"(d[0]), "+f"(d[1]), "+f"(d[2]), "+f"(d[3])
        : "r"(a[0]), "r"(a[1]), "r"(a[2]), "r"(a[3]), "r"(b[0]), "r"(b[1]));
}

// ===========================================================================
// K0: dtype detect + reset progress (every replay)
// ===========================================================================
__global__ void k_init(const void *xraw) {
    if (threadIdx.x == 0) {
        const unsigned int *xi = (const unsigned int *)xraw;
        int i64 = 1;
        for (int i = 0; i < 64; i++)
            if (xi[2 * i + 1] != 0u) { i64 = 0; break; }
        g_xlong = i64;
    }
    if (threadIdx.x < B_) g_prog[threadIdx.x] = 0;
}

// ===========================================================================
// K1a: embedding gather -> bf16 hi/lo input matrix (m = t*16+b)
// ===========================================================================
__global__ void __launch_bounds__(256) k_gather(
    const void *xraw, const float *embx, const float *embl)
{
    const int t = blockIdx.x;
    __shared__ int xs[B_], ls[B_];
    const int tid = threadIdx.x;

    if (tid < 32) {
        int b = tid >> 1, j = tid & 1;
        long long e = (long long)b * (T_ * 2) + t * 2 + j;
        int v;
        if (g_xlong) v = (int)((const long long *)xraw)[e];
        else         v = ((const int *)xraw)[e];
        if (j == 0) xs[b] = v; else ls[b] = v;
    }
    __syncthreads();

    for (int idx = tid; idx < B_ * 256; idx += 256) {
        int b = idx >> 8, k = idx & 255;
        float v = (k < E_) ? embx[xs[b] * E_ + k] : embl[ls[b] * E_ + (k - E_)];
        __nv_bfloat16 h = __float2bfloat16(v);
        __nv_bfloat16 lo = __float2bfloat16(v - __bfloat162float(h));
        size_t e = ((size_t)t * B_ + b) * 256 + k;
        g_Ih[e] = h;
        g_Il[e] = lo;
    }
}

// ===========================================================================
// K1b: W_ih -> bf16 hi/lo
// ===========================================================================
__global__ void __launch_bounds__(256) k_splitW(const float *Wih)
{
    for (int idx = blockIdx.x * 256 + threadIdx.x; idx < (G4_ * H_) / 4;
         idx += gridDim.x * 256) {
        float4 v = ((const float4 *)Wih)[idx];
        size_t e = (size_t)idx * 4;
        __nv_bfloat162 h01 = __floats2bfloat162_rn(v.x, v.y);
        __nv_bfloat162 h23 = __floats2bfloat162_rn(v.z, v.w);
        __nv_bfloat162 l01 = __floats2bfloat162_rn(v.x - __bfloat162float(h01.x),
                                                   v.y - __bfloat162float(h01.y));
        __nv_bfloat162 l23 = __floats2bfloat162_rn(v.z - __bfloat162float(h23.x),
                                                   v.w - __bfloat162float(h23.y));
        *(__nv_bfloat162 *)(g_Wh + e)     = h01;
        *(__nv_bfloat162 *)(g_Wh + e + 2) = h23;
        *(__nv_bfloat162 *)(g_Wl + e)     = l01;
        *(__nv_bfloat162 *)(g_Wl + e + 2) = l23;
    }
}

// ===========================================================================
// K1d: fc_w -> bf16 hi/lo (padded to 8064) — runs BEFORE k_lstm
// ===========================================================================
#define TOT4B ((NPAD * H_) / 4)

__global__ void __launch_bounds__(256) k_splitB(const float *fcw)
{
    for (size_t j = (size_t)blockIdx.x * blockDim.x + threadIdx.x;
         j < TOT4B; j += (size_t)gridDim.x * blockDim.x) {
        size_t e = j * 4;
        int n = (int)(e >> 8), k = (int)(e & 255);
        float4 v = make_float4(0.f, 0.f, 0.f, 0.f);
        if (n < NC_) v = *(const float4 *)(fcw + (size_t)n * H_ + k);
        __nv_bfloat162 h01 = __floats2bfloat162_rn(v.x, v.y);
        __nv_bfloat162 h23 = __floats2bfloat162_rn(v.z, v.w);
        __nv_bfloat162 l01 = __floats2bfloat162_rn(v.x - __bfloat162float(h01.x),
                                                   v.y - __bfloat162float(h01.y));
        __nv_bfloat162 l23 = __floats2bfloat162_rn(v.z - __bfloat162float(h23.x),
                                                   v.w - __bfloat162float(h23.y));
        *(__nv_bfloat162 *)(g_Bh + e)     = h01;
        *(__nv_bfloat162 *)(g_Bh + e + 2) = h23;
        *(__nv_bfloat162 *)(g_Bl + e)     = l01;
        *(__nv_bfloat162 *)(g_Bl + e + 2) = l23;
    }
}

// ===========================================================================
// K1c: input projection GEMM via bf16x3 tensor cores (3-stage, 256 thr)
// ===========================================================================
#define BSTRD 24
#define STAGE_ELEMS (4 * 128 * BSTRD)

__global__ void __launch_bounds__(256) k_proj(const float *bih, const float *bhh)
{
    extern __shared__ __align__(16) __nv_bfloat16 smd[];

    const int bn = blockIdx.x * 128;
    const int bm = blockIdx.y * 128;

    const int tid = threadIdx.x;
    const int w = tid >> 5, l = tid & 31;
    const int wm = w & 1, wn = w >> 1;
    const int g = l >> 2, tig = l & 3;

    float acc[4][4][4];
#pragma unroll
    for (int i = 0; i < 4; i++)
#pragma unroll
        for (int j = 0; j < 4; j++)
#pragma unroll
            for (int c = 0; c < 4; c++) acc[i][j][c] = 0.0f;

    const __nv_bfloat16 *gsrc0 = g_Ih + (size_t)bm * H_;
    const __nv_bfloat16 *gsrc1 = g_Il + (size_t)bm * H_;
    const __nv_bfloat16 *gsrc2 = g_Wh + (size_t)bn * H_;
    const __nv_bfloat16 *gsrc3 = g_Wl + (size_t)bn * H_;

#define LOAD_CHUNK_P(kc, st) do {                                            \
    int k0 = (kc) * 16;                                                      \
    _Pragma("unroll")                                                        \
    for (int i = 0; i < 4; i++) {                                            \
        int s = i * 256 + tid;                                               \
        int tile = s >> 8;                                                   \
        int rr = (s >> 1) & 127;                                             \
        int cc = s & 1;                                                      \
        const __nv_bfloat16 *src =                                           \
            (tile == 0 ? gsrc0 : tile == 1 ? gsrc1 : tile == 2 ? gsrc2 : gsrc3) \
            + (size_t)rr * H_ + k0 + cc * 8;                                 \
        uint32_t dst = smem_u32(smd + (st) * STAGE_ELEMS                     \
                                + tile * (128 * BSTRD) + rr * BSTRD + cc * 8); \
        asm volatile("cp.async.cg.shared.global [%0], [%1], 16;"             \
                     :: "r"(dst), "l"(src));                                 \
    }                                                                        \
    asm volatile("cp.async.commit_group;");                                  \
} while (0)

    LOAD_CHUNK_P(0, 0);
    LOAD_CHUNK_P(1, 1);
    int st = 0, ld_st = 2;
    for (int kc = 0; kc < 16; kc++) {
        if (kc < 15) asm volatile("cp.async.wait_group 1;");
        else         asm volatile("cp.async.wait_group 0;");
        __syncthreads();
        if (kc + 2 < 16) {
            LOAD_CHUNK_P(kc + 2, ld_st);
            ld_st = (ld_st == 2) ? 0 : ld_st + 1;
        }

        const __nv_bfloat16 *Ah_s = smd + st * STAGE_ELEMS;
        const __nv_bfloat16 *Al_s = Ah_s + 128 * BSTRD;
        const __nv_bfloat16 *Bh_s = Ah_s + 2 * 128 * BSTRD;
        const __nv_bfloat16 *Bl_s = Ah_s + 3 * 128 * BSTRD;

        uint32_t ah[4][4], al[4][4], bh[4][2], bl[4][2];
#pragma unroll
        for (int i = 0; i < 4; i++) {
            int arow = (wm * 64 + i * 16 + g) * BSTRD + 2 * tig;
            ah[i][0] = *(const uint32_t *)(Ah_s + arow);
            ah[i][1] = *(const uint32_t *)(Ah_s + arow + 8 * BSTRD);
            ah[i][2] = *(const uint32_t *)(Ah_s + arow + 8);
            ah[i][3] = *(const uint32_t *)(Ah_s + arow + 8 * BSTRD + 8);
            al[i][0] = *(const uint32_t *)(Al_s + arow);
            al[i][1] = *(const uint32_t *)(Al_s + arow + 8 * BSTRD);
            al[i][2] = *(const uint32_t *)(Al_s + arow + 8);
            al[i][3] = *(const uint32_t *)(Al_s + arow + 8 * BSTRD + 8);
        }
#pragma unroll
        for (int j = 0; j < 4; j++) {
            int brow = (wn * 32 + j * 8 + g) * BSTRD + 2 * tig;
            bh[j][0] = *(const uint32_t *)(Bh_s + brow);
            bh[j][1] = *(const uint32_t *)(Bh_s + brow + 8);
            bl[j][0] = *(const uint32_t *)(Bl_s + brow);
            bl[j][1] = *(const uint32_t *)(Bl_s + brow + 8);
        }
#pragma unroll
        for (int i = 0; i < 4; i++)
#pragma unroll
            for (int j = 0; j < 4; j++) {
                mma_bf16(acc[i][j], ah[i], bh[j]);
                mma_bf16(acc[i][j], al[i], bh[j]);
                mma_bf16(acc[i][j], ah[i], bl[j]);
            }

        st = (st == 2) ? 0 : st + 1;
    }

#pragma unroll
    for (int i = 0; i < 4; i++) {
        int m0 = bm + wm * 64 + i * 16 + g;
#pragma unroll
        for (int j = 0; j < 4; j++) {
            int n0 = bn + wn * 32 + j * 8 + 2 * tig;
            float bx = bih[n0] + bhh[n0];
            float by = bih[n0 + 1] + bhh[n0 + 1];
            *(float2 *)(g_xproj + (size_t)m0 * G4_ + n0) =
                make_float2(acc[i][j][0] + bx, acc[i][j][1] + by);
            *(float2 *)(g_xproj + (size_t)(m0 + 8) * G4_ + n0) =
                make_float2(acc[i][j][2] + bx, acc[i][j][3] + by);
        }
    }
}

// ===========================================================================
// K2: LSTM recurrence — proven round-11 config + direct bf16 h store +
// progress publication + PDL trigger (all CTAs, once resident).
// ===========================================================================
__global__ void __launch_bounds__(512, 1) __cluster_dims__(8, 1, 1)
k_lstm(const float *Whh)
{
    const int cta = blockIdx.x;
    const int b   = cta >> 3;
    const int grp = cta & 7;
    const int tid = threadIdx.x;
    const int r = tid >> 2;
    const int q = tid & 3;
    const int gate = r >> 5, lh = r & 31;
    const int row_g = gate * H_ + grp * 32 + lh;

    __shared__ __align__(16) float h_buf[2][272];
    __shared__ float gates_s[128];
    __shared__ __align__(8) u64 mbar[2];

    u64 w2[32];
    {
        const float *wp = Whh + (size_t)row_g * H_ + q * 64;
#pragma unroll
        for (int j = 0; j < 32; j++) w2[j] = *(const u64 *)(wp + 2 * j);
    }

    if (tid < 136) ((float4 *)h_buf)[tid] = make_float4(0.f, 0.f, 0.f, 0.f);

    const uint32_t mbase = smem_u32(&mbar[0]);
    const uint32_t hbase = smem_u32(&h_buf[0][0]);
    if (tid == 0) { mbar_init(mbase, 1); mbar_init(mbase + 8, 1); }
    __syncthreads();
    if (tid == 0) { mbar_expect_tx(mbase, 1024); mbar_expect_tx(mbase + 8, 1024); }

    uint32_t peer_h[8], peer_m[8];
    {
        int k = grp * 32 + 2 * (tid & 15);
        uint32_t off = (uint32_t)(((k >> 6) * 68 + (k & 63)) * 4);
#pragma unroll
        for (int pc = 0; pc < 8; pc++) {
            peer_h[pc] = mapa_u32(hbase, (uint32_t)pc) + off;
            peer_m[pc] = mapa_u32(mbase, (uint32_t)pc);
        }
    }

    float xp = (q == 0) ? g_xproj[(size_t)b * G4_ + row_g] : 0.0f;
    float creg = 0.0f;
    __syncthreads();
    CLUSTER_SYNC();

    // all CTAs resident + initialized -> let dependent k_fc start flowing
    asm volatile("griddepcontrol.launch_dependents;" ::: "memory");

    uint32_t ph0 = 0, ph1 = 0;

    for (int t = 0; t < T_; t++) {
        if (t > 0) {
            int p = t & 1;
            uint32_t mb = mbase + (uint32_t)p * 8;
            if (tid < 32) {
                if (p) mbar_wait(mb, ph1);
                else   mbar_wait(mb, ph0);
            }
            if (p) ph1 ^= 1; else ph0 ^= 1;
            asm volatile("bar.sync 0;" ::: "memory");
            if (tid == 0 && t + 2 < T_) mbar_expect_tx(mb, 1024);
        }

        uint32_t hq = hbase + (uint32_t)(t & 1) * 1088 + (uint32_t)q * 272;
        u64 a0 = 0, a1 = 0, a2 = 0, a3 = 0;
#pragma unroll
        for (int jj = 0; jj < 16; jj += 2) {
            u64 x0, y0, x1, y1;
            lds_v2u64(hq + jj * 16, x0, y0);
            lds_v2u64(hq + jj * 16 + 16, x1, y1);
            ffma2(a0, w2[2 * jj + 0], x0);
            ffma2(a1, w2[2 * jj + 1], y0);
            ffma2(a2, w2[2 * jj + 2], x1);
            ffma2(a3, w2[2 * jj + 3], y1);
        }
        float2 s0 = funpack(a0), s1 = funpack(a1), s2 = funpack(a2), s3 = funpack(a3);
        float sum = ((s0.x + s0.y) + (s1.x + s1.y)) + ((s2.x + s2.y) + (s3.x + s3.y));
        sum += __shfl_xor_sync(0xffffffffu, sum, 1);
        sum += __shfl_xor_sync(0xffffffffu, sum, 2);
        if (q == 0) gates_s[r] = sum + xp;

        float xp_n = 0.0f;
        if (q == 0 && t + 1 < T_)
            xp_n = g_xproj[(size_t)(t + 1) * (B_ * G4_) + b * G4_ + row_g];

        __syncthreads();

        if (tid < 32) {
            float iv = sigm(gates_s[tid]);
            float fv = sigm(gates_s[32 + tid]);
            float gv = tanh_f(gates_s[64 + tid]);
            float ov = sigm(gates_s[96 + tid]);
            float cn = fv * creg + iv * gv;
            creg = cn;
            float hn = ov * tanh_f(cn);
            // direct bf16 hi/lo store (replaces g_hs + split A-pass)
            __nv_bfloat16 hh = __float2bfloat16(hn);
            __nv_bfloat16 hl = __float2bfloat16(hn - __bfloat162float(hh));
            size_t eo = ((size_t)b * T_ + t) * H_ + grp * 32 + tid;
            g_Ah[eo] = hh;
            g_Al[eo] = hl;
            float he = __shfl_sync(0xffffffffu, hn, 2 * (tid & 15));
            float ho = __shfl_sync(0xffffffffu, hn, 2 * (tid & 15) + 1);
            if (tid < 16 && t < T_ - 1) {
                u64 hv2 = fpack(he, ho);
                uint32_t bo = (uint32_t)((t + 1) & 1) * 1088;
                uint32_t mo = (uint32_t)((t + 1) & 1) * 8;
#pragma unroll
                for (int pc = 0; pc < 8; pc++)
                    st_async_u64(peer_h[pc] + bo, hv2, peer_m[pc] + mo);
            }
            __syncwarp();
            if (tid == 0 && (t & 15) == 15) {
                __threadfence();              // release all lanes' g_Ah/g_Al stores
                atomicAdd(&g_prog[b], 1);     // 8 increments per CTA per 128-chunk
            }
        }
        xp = xp_n;
    }
    CLUSTER_SYNC();
}

// ===========================================================================
// K3: FC GEMM — proven bf16x3 3-stage pipeline; launched with PDL so its
// blocks run on idle SMs while k_lstm executes. Blocks ordered chunk-major;
// tid0 spin-waits per-batch progress (acquire) before the tile.
// ===========================================================================
__global__ void __launch_bounds__(256) k_fc(const float *fcb, float *out)
{
    extern __shared__ __align__(16) __nv_bfloat16 smd[];
    __shared__ int ready;

    const int tk = blockIdx.x;           // chunk-major ordering
    const int tc = tk / (B_ * NTILE_N);
    const int rr2 = tk - tc * (B_ * NTILE_N);
    const int b  = rr2 / NTILE_N;
    const int ni = rr2 - b * NTILE_N;
    const int bm = b * T_ + tc * 128;
    const int bn = ni * 128;

    const int tid = threadIdx.x;
    if (tid == 0) {
        int need = 64 * (tc + 1);
        while (ld_acq(&g_prog[b]) < need) { }
        ready = 1;
    }
    __syncthreads();

    const int w = tid >> 5, l = tid & 31;
    const int wm = w & 1, wn = w >> 1;
    const int g = l >> 2, tig = l & 3;

    float acc[4][4][4];
#pragma unroll
    for (int i = 0; i < 4; i++)
#pragma unroll
        for (int j = 0; j < 4; j++)
#pragma unroll
            for (int c = 0; c < 4; c++) acc[i][j][c] = 0.0f;

    const __nv_bfloat16 *gsrc0 = g_Ah + (size_t)bm * H_;
    const __nv_bfloat16 *gsrc1 = g_Al + (size_t)bm * H_;
    const __nv_bfloat16 *gsrc2 = g_Bh + (size_t)bn * H_;
    const __nv_bfloat16 *gsrc3 = g_Bl + (size_t)bn * H_;

#define LOAD_CHUNK(kc, st) do {                                              \
    int k0 = (kc) * 16;                                                      \
    _Pragma("unroll")                                                        \
    for (int i = 0; i < 4; i++) {                                            \
        int s = i * 256 + tid;                                               \
        int tile = s >> 8;                                                   \
        int rr = (s >> 1) & 127;                                             \
        int cc = s & 1;                                                      \
        const __nv_bfloat16 *src =                                           \
            (tile == 0 ? gsrc0 : tile == 1 ? gsrc1 : tile == 2 ? gsrc2 : gsrc3) \
            + (size_t)rr * H_ + k0 + cc * 8;                                 \
        uint32_t dst = smem_u32(smd + (st) * STAGE_ELEMS                     \
                                + tile * (128 * BSTRD) + rr * BSTRD + cc * 8); \
        asm volatile("cp.async.cg.shared.global [%0], [%1], 16;"             \
                     :: "r"(dst), "l"(src));                                 \
    }                                                                        \
    asm volatile("cp.async.commit_group;");                                  \
} while (0)

    LOAD_CHUNK(0, 0);
    LOAD_CHUNK(1, 1);
    int st = 0, ld_st = 2;
    for (int kc = 0; kc < 16; kc++) {
        if (kc < 15) asm volatile("cp.async.wait_group 1;");
        else         asm volatile("cp.async.wait_group 0;");
        __syncthreads();
        if (kc + 2 < 16) {
            LOAD_CHUNK(kc + 2, ld_st);
            ld_st = (ld_st == 2) ? 0 : ld_st + 1;
        }

        const __nv_bfloat16 *Ah_s = smd + st * STAGE_ELEMS;
        const __nv_bfloat16 *Al_s = Ah_s + 128 * BSTRD;
        const __nv_bfloat16 *Bh_s = Ah_s + 2 * 128 * BSTRD;
        const __nv_bfloat16 *Bl_s = Ah_s + 3 * 128 * BSTRD;

        uint32_t ah[4][4], al[4][4], bh[4][2], bl[4][2];
#pragma unroll
        for (int i = 0; i < 4; i++) {
            int arow = (wm * 64 + i * 16 + g) * BSTRD + 2 * tig;
            ah[i][0] = *(const uint32_t *)(Ah_s + arow);
            ah[i][1] = *(const uint32_t *)(Ah_s + arow + 8 * BSTRD);
            ah[i][2] = *(const uint32_t *)(Ah_s + arow + 8);
            ah[i][3] = *(const uint32_t *)(Ah_s + arow + 8 * BSTRD + 8);
            al[i][0] = *(const uint32_t *)(Al_s + arow);
            al[i][1] = *(const uint32_t *)(Al_s + arow + 8 * BSTRD);
            al[i][2] = *(const uint32_t *)(Al_s + arow + 8);
            al[i][3] = *(const uint32_t *)(Al_s + arow + 8 * BSTRD + 8);
        }
#pragma unroll
        for (int j = 0; j < 4; j++) {
            int brow = (wn * 32 + j * 8 + g) * BSTRD + 2 * tig;
            bh[j][0] = *(const uint32_t *)(Bh_s + brow);
            bh[j][1] = *(const uint32_t *)(Bh_s + brow + 8);
            bl[j][0] = *(const uint32_t *)(Bl_s + brow);
            bl[j][1] = *(const uint32_t *)(Bl_s + brow + 8);
        }
#pragma unroll
        for (int i = 0; i < 4; i++)
#pragma unroll
            for (int j = 0; j < 4; j++) {
                mma_bf16(acc[i][j], ah[i], bh[j]);
                mma_bf16(acc[i][j], al[i], bh[j]);
                mma_bf16(acc[i][j], ah[i], bl[j]);
            }

        st = (st == 2) ? 0 : st + 1;
    }

#pragma unroll
    for (int i = 0; i < 4; i++) {
        int m0 = bm + wm * 64 + i * 16 + g;
#pragma unroll
        for (int j = 0; j < 4; j++) {
            int n0 = bn + wn * 32 + j * 8 + 2 * tig;
            if (n0 < NC_) {
                float bx = fcb[n0], by = fcb[n0 + 1];
                *(float2 *)(out + (size_t)m0 * NC_ + n0) =
                    make_float2(acc[i][j][0] + bx, acc[i][j][1] + by);
                *(float2 *)(out + (size_t)(m0 + 8) * NC_ + n0) =
                    make_float2(acc[i][j][2] + bx, acc[i][j][3] + by);
            }
        }
    }
    (void)ready;
}

// ===========================================================================
extern "C" void kernel_launch(void *const *d_in, const int *in_sizes, int n_in,
                              void *d_out, int out_size)
{
    (void)in_sizes; (void)n_in; (void)out_size;
    const void  *x    = d_in[0];
    const float *embx = (const float *)d_in[1];
    const float *embl = (const float *)d_in[2];
    const float *Wih  = (const float *)d_in[3];
    const float *Whh  = (const float *)d_in[4];
    const float *bih  = (const float *)d_in[5];
    const float *bhh  = (const float *)d_in[6];
    const float *fcw  = (const float *)d_in[7];
    const float *fcb  = (const float *)d_in[8];
    float *out = (float *)d_out;

    const int fc_smem = 3 * STAGE_ELEMS * (int)sizeof(__nv_bfloat16);  // 73728
    cudaFuncSetAttribute(k_proj, cudaFuncAttributeMaxDynamicSharedMemorySize, fc_smem);
    cudaFuncSetAttribute(k_fc,   cudaFuncAttributeMaxDynamicSharedMemorySize, fc_smem);

    k_init<<<1, 32>>>(x);
    k_gather<<<T_, 256>>>(x, embx, embl);
    k_splitW<<<64, 256>>>(Wih);
    k_splitB<<<512, 256>>>(fcw);
    k_proj<<<dim3(G4_ / 128, (B_ * T_) / 128), 256, fc_smem>>>(bih, bhh);
    k_lstm<<<B_ * 8, 512>>>(Whh);

    // k_fc with programmatic dependent launch: starts on idle SMs while
    // k_lstm runs (after its griddepcontrol.launch_dependents).
    cudaLaunchConfig_t cfg = {};
    cfg.gridDim = dim3(NTICKETS, 1, 1);
    cfg.blockDim = dim3(256, 1, 1);
    cfg.dynamicSmemBytes = fc_smem;
    cfg.stream = 0;
    cudaLaunchAttribute at[1];
    at[0].id = cudaLaunchAttributeProgrammaticStreamSerialization;
    at[0].val.programmaticStreamSerializationAllowed = 1;
    cfg.attrs = at;
    cfg.numAttrs = 1;
    cudaLaunchKernelEx(&cfg, k_fc, fcb, out);
}